// round 15
// baseline (speedup 1.0000x reference)
#include <cuda_runtime.h>
#include <cuda_fp16.h>

#define BATCH  2048
#define LATENT 64
#define NJ     64           // number of j-chunks
#define JC     (BATCH/NJ)   // 32 j per chunk
#define IB     256          // threads per CTA (8 warps)
#define NP     (LATENT/2)   // 32 pairs
#define NQ     (LATENT/4)   // 16 quad-records
#define IPB    256          // i's per CTA (8 warps x 32 i/warp)

#define LOG2E_F   1.4426950408889634f
#define LN2_F     0.6931471805599453f
#define LOG2PI_F  1.8378770664093453f

// ---- device scratch (static; no allocation anywhere) ----
__device__ unsigned int d_accP[NJ*NP*BATCH]; // per-(chunk,pair,i) half2 partial sums (16MB)
__device__ float d_m2P[NJ*BATCH];            // per-(chunk,i) max (log2 domain)
__device__ float d_t2P[NJ*BATCH];            // per-(chunk,i) scaled sum
__device__ float d_lqp[NP*BATCH];            // per-(pair,i) lg2(s0)+lg2(s1)
__device__ float d_val[BATCH];               // per-i final value
__device__ unsigned int d_ctr;               // last-block counter

// ---- tiny PTX helpers ----
__device__ __forceinline__ float ex2f(float x){ float r; asm("ex2.approx.f32 %0, %1;" : "=f"(r) : "f"(x)); return r; }
__device__ __forceinline__ float lg2f(float x){ float r; asm("lg2.approx.f32 %0, %1;" : "=f"(r) : "f"(x)); return r; }
typedef unsigned long long u64;
__device__ __forceinline__ u64 fma2(u64 a, u64 b, u64 c){ u64 d; asm("fma.rn.f32x2 %0, %1, %2, %3;" : "=l"(d) : "l"(a), "l"(b), "l"(c)); return d; }
__device__ __forceinline__ u64 add2(u64 a, u64 b){ u64 d; asm("add.rn.f32x2 %0, %1, %2;" : "=l"(d) : "l"(a), "l"(b)); return d; }
__device__ __forceinline__ void upk(u64 v, float& lo, float& hi){ asm("mov.b64 {%0, %1}, %2;" : "=f"(lo), "=f"(hi) : "l"(v)); }
__device__ __forceinline__ u64 pkf2(float lo, float hi){ u64 r; asm("mov.b64 %0, {%1, %2};" : "=l"(r) : "f"(lo), "f"(hi)); return r; }
__device__ __forceinline__ unsigned cvt_h2(float a, float b){ unsigned r; asm("cvt.rn.f16x2.f32 %0, %1, %2;" : "=r"(r) : "f"(b), "f"(a)); return r; }
__device__ __forceinline__ unsigned hex2(unsigned x){ unsigned r; asm("ex2.approx.f16x2 %0, %1;" : "=r"(r) : "r"(x)); return r; }
__device__ __forceinline__ unsigned hadd2(unsigned a, unsigned b){ unsigned r; asm("add.rn.f16x2 %0, %1, %2;" : "=r"(r) : "r"(a), "r"(b)); return r; }

// ==== kernel 1: main pass (268M exps), l-half split + 2 i's per thread ====
// grid (BATCH/IPB, NJ) = (8, 64) = 512 CTAs of 256 threads (8 warps).
// Inner loop identical to R11; only CTA geometry changed (halves prep duplication).
// lane = (il, half): il = lane&15, half = lane>>4 (l in [half*32, half*32+32))
// thread handles i0 = base + il and i1 = base + 16 + il.
__global__ void __launch_bounds__(IB, 2) btc_main(const float* __restrict__ z,
                                                  const float* __restrict__ zm,
                                                  const float* __restrict__ zl)
{
    __shared__ float sC[JC*NQ*12];   // 24KB: per (j,quad) 48B record {A01,B01}{A23,B23}{G01,G23}

    const int ch    = blockIdx.y;
    const int jbase = ch * JC;
    const int lane  = threadIdx.x & 31;
    const int wid   = threadIdx.x >> 5;
    const int half  = lane >> 4;
    const int il    = lane & 15;
    const int ibase = blockIdx.x * IPB + wid * 32;
    const int i0    = ibase + il;
    const int i1    = ibase + 16 + il;

    if (blockIdx.x == 0 && blockIdx.y == 0 && threadIdx.x == 0) d_ctr = 0;

    // ---- inline coefficient prep for this chunk's 32 j x 64 l ----
    #pragma unroll
    for (int k = 0; k < (JC*LATENT)/IB; k++) {
        int idx = threadIdx.x + k*IB;          // coalesced LDG
        int j = idx >> 6, l = idx & 63;
        float m  = zm[(jbase + j)*LATENT + l];
        float lv = zl[(jbase + j)*LATENT + l];
        float invs = ex2f(-lv * LOG2E_F);      // exp(-lv)
        float a = -0.5f * invs;
        int q = l >> 2;
        int aoff = (l & 2) * 2 + (l & 1);      // 0,1,4,5
        float* rec = &sC[(j*NQ + q)*12];
        rec[aoff    ] = a * LOG2E_F;                               // A
        rec[aoff + 2] = invs * m * LOG2E_F;                        // B
        rec[8 + (l&3)] = (a*m*m - 0.5f*(lv + LOG2PI_F)) * LOG2E_F; // G
    }
    __syncthreads();

    // ---- two half z-rows in registers, packed f32x2 (16 u64 each) ----
    u64 zr0[16], zr1[16];
    {
        const float4* za = (const float4*)(z + i0*LATENT + half*32);
        const float4* zb = (const float4*)(z + i1*LATENT + half*32);
        #pragma unroll
        for (int q = 0; q < 8; q++) {
            float4 v = za[q];
            zr0[2*q] = pkf2(v.x, v.y); zr0[2*q+1] = pkf2(v.z, v.w);
            float4 w = zb[q];
            zr1[2*q] = pkf2(w.x, w.y); zr1[2*q+1] = pkf2(w.z, w.w);
        }
    }

    unsigned hacc0[16], hacc1[16];
    #pragma unroll
    for (int p = 0; p < 16; p++) { hacc0[p] = 0u; hacc1[p] = 0u; }

    float M0 = -1e30f, T0 = 0.f, M1 = -1e30f, T1 = 0.f;

    for (int jl = 0; jl < JC; jl++) {
        const ulonglong2* r2 = (const ulonglong2*)&sC[jl*NQ*12];
        u64 s20 = 0ull, s21 = 0ull;
        #pragma unroll
        for (int q = 0; q < 8; q++) {
            const int qg = half*8 + q;           // this lane's global quad
            ulonglong2 ab0 = r2[3*qg    ];       // {A01, B01}
            ulonglong2 ab1 = r2[3*qg + 1];       // {A23, B23}
            ulonglong2 gg  = r2[3*qg + 2];       // {G01, G23}
            // ---- i0 ----
            {
                u64 t0 = fma2(ab0.x, zr0[2*q  ], ab0.y);
                u64 pa = fma2(t0,    zr0[2*q  ], gg.x);
                u64 t1 = fma2(ab1.x, zr0[2*q+1], ab1.y);
                u64 pb = fma2(t1,    zr0[2*q+1], gg.y);
                s20 = add2(s20, pa);
                s20 = add2(s20, pb);
                float a0, a1, b0, b1;
                upk(pa, a0, a1); upk(pb, b0, b1);
                hacc0[2*q  ] = hadd2(hacc0[2*q  ], hex2(cvt_h2(a0, a1)));
                hacc0[2*q+1] = hadd2(hacc0[2*q+1], hex2(cvt_h2(b0, b1)));
            }
            // ---- i1 ----
            {
                u64 t0 = fma2(ab0.x, zr1[2*q  ], ab0.y);
                u64 pa = fma2(t0,    zr1[2*q  ], gg.x);
                u64 t1 = fma2(ab1.x, zr1[2*q+1], ab1.y);
                u64 pb = fma2(t1,    zr1[2*q+1], gg.y);
                s21 = add2(s21, pa);
                s21 = add2(s21, pb);
                float a0, a1, b0, b1;
                upk(pa, a0, a1); upk(pb, b0, b1);
                hacc1[2*q  ] = hadd2(hacc1[2*q  ], hex2(cvt_h2(a0, a1)));
                hacc1[2*q+1] = hadd2(hacc1[2*q+1], hex2(cvt_h2(b0, b1)));
            }
        }
        {
            float s0, s1; upk(s20, s0, s1);
            float Sh = s0 + s1;
            float S  = Sh + __shfl_xor_sync(0xffffffffu, Sh, 16);
            float nM = fmaxf(M0, S);
            T0 = T0 * ex2f(M0 - nM) + ex2f(S - nM);
            M0 = nM;
        }
        {
            float s0, s1; upk(s21, s0, s1);
            float Sh = s0 + s1;
            float S  = Sh + __shfl_xor_sync(0xffffffffu, Sh, 16);
            float nM = fmaxf(M1, S);
            T1 = T1 * ex2f(M1 - nM) + ex2f(S - nM);
            M1 = nM;
        }
    }

    // write partials (coalesced per half-warp)
    #pragma unroll
    for (int p = 0; p < 16; p++) {
        d_accP[(ch*NP + half*16 + p)*BATCH + i0] = hacc0[p];
        d_accP[(ch*NP + half*16 + p)*BATCH + i1] = hacc1[p];
    }
    if (half == 0) {
        d_m2P[ch*BATCH + i0] = M0;
        d_t2P[ch*BATCH + i0] = T0;
        d_m2P[ch*BATCH + i1] = M1;
        d_t2P[ch*BATCH + i1] = T1;
    }
}

// ==== kernel 2: stage-1 reduce. grid (32, 32) = 1024 CTAs ==== [R11-exact]
__global__ void __launch_bounds__(256) btc_stage1()
{
    __shared__ float sP[4][64][2];

    const int li = threadIdx.x & 63;
    const int g  = threadIdx.x >> 6;
    const int i  = blockIdx.x * 64 + li;
    const int p  = blockIdx.y;

    float s0 = 0.f, s1 = 0.f;
    #pragma unroll
    for (int c = 0; c < NJ/4; c++) {
        int chn = g*(NJ/4) + c;
        __half2 h = *reinterpret_cast<const __half2*>(&d_accP[(chn*NP + p)*BATCH + i]);
        float2 f = __half22float2(h);
        s0 += f.x; s1 += f.y;
    }
    sP[g][li][0] = s0;
    sP[g][li][1] = s1;
    __syncthreads();

    if (g == 0) {
        float t0 = s0 + sP[1][li][0] + sP[2][li][0] + sP[3][li][0];
        float t1 = s1 + sP[1][li][1] + sP[2][li][1] + sP[3][li][1];
        d_lqp[p*BATCH + i] = lg2f(t0) + lg2f(t1);
    }
}

// ==== kernel 3: finish v2 — grid 64 x 256. CTA = 32 i's x 8 groups ==== [R11-exact]
__global__ void __launch_bounds__(256) btc_finish(const float* __restrict__ zm,
                                                  const float* __restrict__ zl,
                                                  float* __restrict__ out)
{
    __shared__ float s_lqp[8][32];
    __shared__ float s_kl [8][32];
    __shared__ float s_m  [8][32];
    __shared__ float s_t  [8][32];
    __shared__ float sh[256];
    __shared__ unsigned s_done;

    const int li = threadIdx.x & 31;
    const int g  = threadIdx.x >> 5;
    const int i  = blockIdx.x * 32 + li;

    float lqp = 0.f;
    #pragma unroll
    for (int pp = 0; pp < 4; pp++)
        lqp += d_lqp[(g*4 + pp)*BATCH + i];
    s_lqp[g][li] = lqp;

    float M = -1e30f, T = 0.f;
    #pragma unroll
    for (int cc = 0; cc < 8; cc++) {
        const int chn = g*8 + cc;
        float m = d_m2P[chn*BATCH + i];
        float t = d_t2P[chn*BATCH + i];
        float nM = fmaxf(M, m);
        T = T * ex2f(M - nM) + t * ex2f(m - nM);
        M = nM;
    }
    s_m[g][li] = M;
    s_t[g][li] = T;

    {
        float kl = 0.f;
        const float4* m4 = (const float4*)(zm + i*LATENT + g*8);
        const float4* l4 = (const float4*)(zl + i*LATENT + g*8);
        #pragma unroll
        for (int q = 0; q < 2; q++) {
            float4 mm = m4[q], lv = l4[q];
            kl += mm.x*mm.x + ex2f(lv.x*LOG2E_F) - lv.x
                + mm.y*mm.y + ex2f(lv.y*LOG2E_F) - lv.y
                + mm.z*mm.z + ex2f(lv.z*LOG2E_F) - lv.z
                + mm.w*mm.w + ex2f(lv.w*LOG2E_F) - lv.w - 4.f;
        }
        s_kl[g][li] = kl;
    }
    __syncthreads();

    if (g == 0) {
        float lqp_tot = 0.f, kl_tot = 0.f;
        float Mf = -1e30f, Tf = 0.f;
        #pragma unroll
        for (int gg = 0; gg < 8; gg++) {
            lqp_tot += s_lqp[gg][li];
            kl_tot  += s_kl [gg][li];
            float m = s_m[gg][li], t = s_t[gg][li];
            float nM = fmaxf(Mf, m);
            Tf = Tf * ex2f(Mf - nM) + t * ex2f(m - nM);
            Mf = nM;
        }
        float lq2 = Mf + lg2f(Tf);
        d_val[i] = 5.0f * LN2_F * (lq2 - lqp_tot) + 0.5f * kl_tot;
    }
    __syncthreads();

    __threadfence();
    if (threadIdx.x == 0) s_done = atomicAdd(&d_ctr, 1);
    __syncthreads();
    if (s_done == (BATCH/32) - 1) {
        __threadfence();
        float s = 0.f;
        for (int k = threadIdx.x; k < BATCH; k += 256) s += d_val[k];
        sh[threadIdx.x] = s;
        __syncthreads();
        for (int st = 128; st > 0; st >>= 1) {
            if (threadIdx.x < st) sh[threadIdx.x] += sh[threadIdx.x + st];
            __syncthreads();
        }
        if (threadIdx.x == 0) out[0] = sh[0] / (float)BATCH;
    }
}

extern "C" void kernel_launch(void* const* d_in, const int* in_sizes, int n_in,
                              void* d_out, int out_size)
{
    const float* z  = (const float*)d_in[0];
    const float* zm = (const float*)d_in[1];
    const float* zl = (const float*)d_in[2];
    (void)in_sizes; (void)n_in; (void)out_size;

    btc_main<<<dim3(BATCH/IPB, NJ), IB>>>(z, zm, zl);
    btc_stage1<<<dim3(BATCH/64, NP), 256>>>();
    btc_finish<<<BATCH/32, 256>>>(zm, zl, (float*)d_out);
}

// round 16
// speedup vs baseline: 1.0856x; 1.0856x over previous
#include <cuda_runtime.h>
#include <cuda_fp16.h>

#define BATCH  2048
#define LATENT 64
#define NJ     64           // number of j-chunks
#define JC     (BATCH/NJ)   // 32 j per chunk
#define IB     128          // threads per CTA (4 warps)
#define NP     (LATENT/2)   // 32 pairs
#define NQ     (LATENT/4)   // 16 quad-records
#define IPB    128          // i's per CTA (4 warps x 32 i/warp)

#define LOG2E_F   1.4426950408889634f
#define LN2_F     0.6931471805599453f
#define LOG2PI_F  1.8378770664093453f

// ---- device scratch (static; no allocation anywhere) ----
__device__ unsigned int d_accP[NJ*NP*BATCH]; // per-(chunk,pair,i) half2 partial sums (16MB)
__device__ float d_m2P[NJ*BATCH];            // per-(chunk,i) max (log2 domain)
__device__ float d_t2P[NJ*BATCH];            // per-(chunk,i) scaled sum
__device__ float d_lqp[NP*BATCH];            // per-(pair,i) lg2(s0)+lg2(s1)
__device__ float d_val[BATCH];               // per-i final value
__device__ unsigned int d_ctr;               // last-block counter

// ---- tiny PTX helpers ----
__device__ __forceinline__ float ex2f(float x){ float r; asm("ex2.approx.f32 %0, %1;" : "=f"(r) : "f"(x)); return r; }
__device__ __forceinline__ float lg2f(float x){ float r; asm("lg2.approx.f32 %0, %1;" : "=f"(r) : "f"(x)); return r; }
typedef unsigned long long u64;
__device__ __forceinline__ u64 fma2(u64 a, u64 b, u64 c){ u64 d; asm("fma.rn.f32x2 %0, %1, %2, %3;" : "=l"(d) : "l"(a), "l"(b), "l"(c)); return d; }
__device__ __forceinline__ u64 add2(u64 a, u64 b){ u64 d; asm("add.rn.f32x2 %0, %1, %2;" : "=l"(d) : "l"(a), "l"(b)); return d; }
__device__ __forceinline__ void upk(u64 v, float& lo, float& hi){ asm("mov.b64 {%0, %1}, %2;" : "=f"(lo), "=f"(hi) : "l"(v)); }
__device__ __forceinline__ u64 pkf2(float lo, float hi){ u64 r; asm("mov.b64 %0, {%1, %2};" : "=l"(r) : "f"(lo), "f"(hi)); return r; }
__device__ __forceinline__ unsigned cvt_h2(float a, float b){ unsigned r; asm("cvt.rn.f16x2.f32 %0, %1, %2;" : "=r"(r) : "f"(b), "f"(a)); return r; }
__device__ __forceinline__ unsigned hex2(unsigned x){ unsigned r; asm("ex2.approx.f16x2 %0, %1;" : "=r"(r) : "r"(x)); return r; }
__device__ __forceinline__ unsigned hadd2(unsigned a, unsigned b){ unsigned r; asm("add.rn.f16x2 %0, %1, %2;" : "=r"(r) : "r"(a), "r"(b)); return r; }

// ==== kernel 1: main pass (268M exps), l-half split + 2 i's per thread ====
// [R11-exact] grid (BATCH/IPB, NJ) = (16, 64). CTA = 128 i's x one 32-j chunk.
// lane = (il, half): il = lane&15, half = lane>>4 (l in [half*32, half*32+32))
// thread handles i0 = base + il and i1 = base + 16 + il.
__global__ void __launch_bounds__(IB, 4) btc_main(const float* __restrict__ z,
                                                  const float* __restrict__ zm,
                                                  const float* __restrict__ zl)
{
    __shared__ float sC[JC*NQ*12];   // 24KB: per (j,quad) 48B record {A01,B01}{A23,B23}{G01,G23}

    const int ch    = blockIdx.y;
    const int jbase = ch * JC;
    const int lane  = threadIdx.x & 31;
    const int wid   = threadIdx.x >> 5;
    const int half  = lane >> 4;
    const int il    = lane & 15;
    const int ibase = blockIdx.x * IPB + wid * 32;
    const int i0    = ibase + il;
    const int i1    = ibase + 16 + il;

    if (blockIdx.x == 0 && blockIdx.y == 0 && threadIdx.x == 0) d_ctr = 0;

    // ---- inline coefficient prep for this chunk's 32 j x 64 l ----
    #pragma unroll
    for (int k = 0; k < (JC*LATENT)/IB; k++) {
        int idx = threadIdx.x + k*IB;          // coalesced LDG
        int j = idx >> 6, l = idx & 63;
        float m  = zm[(jbase + j)*LATENT + l];
        float lv = zl[(jbase + j)*LATENT + l];
        float invs = ex2f(-lv * LOG2E_F);      // exp(-lv)
        float a = -0.5f * invs;
        int q = l >> 2;
        int aoff = (l & 2) * 2 + (l & 1);      // 0,1,4,5
        float* rec = &sC[(j*NQ + q)*12];
        rec[aoff    ] = a * LOG2E_F;                               // A
        rec[aoff + 2] = invs * m * LOG2E_F;                        // B
        rec[8 + (l&3)] = (a*m*m - 0.5f*(lv + LOG2PI_F)) * LOG2E_F; // G
    }
    __syncthreads();

    // ---- two half z-rows in registers, packed f32x2 (16 u64 each) ----
    u64 zr0[16], zr1[16];
    {
        const float4* za = (const float4*)(z + i0*LATENT + half*32);
        const float4* zb = (const float4*)(z + i1*LATENT + half*32);
        #pragma unroll
        for (int q = 0; q < 8; q++) {
            float4 v = za[q];
            zr0[2*q] = pkf2(v.x, v.y); zr0[2*q+1] = pkf2(v.z, v.w);
            float4 w = zb[q];
            zr1[2*q] = pkf2(w.x, w.y); zr1[2*q+1] = pkf2(w.z, w.w);
        }
    }

    unsigned hacc0[16], hacc1[16];
    #pragma unroll
    for (int p = 0; p < 16; p++) { hacc0[p] = 0u; hacc1[p] = 0u; }

    float M0 = -1e30f, T0 = 0.f, M1 = -1e30f, T1 = 0.f;

    for (int jl = 0; jl < JC; jl++) {
        const ulonglong2* r2 = (const ulonglong2*)&sC[jl*NQ*12];
        u64 s20 = 0ull, s21 = 0ull;
        #pragma unroll
        for (int q = 0; q < 8; q++) {
            const int qg = half*8 + q;           // this lane's global quad
            ulonglong2 ab0 = r2[3*qg    ];       // {A01, B01}
            ulonglong2 ab1 = r2[3*qg + 1];       // {A23, B23}
            ulonglong2 gg  = r2[3*qg + 2];       // {G01, G23}
            // ---- i0 ----
            {
                u64 t0 = fma2(ab0.x, zr0[2*q  ], ab0.y);
                u64 pa = fma2(t0,    zr0[2*q  ], gg.x);
                u64 t1 = fma2(ab1.x, zr0[2*q+1], ab1.y);
                u64 pb = fma2(t1,    zr0[2*q+1], gg.y);
                s20 = add2(s20, pa);
                s20 = add2(s20, pb);
                float a0, a1, b0, b1;
                upk(pa, a0, a1); upk(pb, b0, b1);
                hacc0[2*q  ] = hadd2(hacc0[2*q  ], hex2(cvt_h2(a0, a1)));
                hacc0[2*q+1] = hadd2(hacc0[2*q+1], hex2(cvt_h2(b0, b1)));
            }
            // ---- i1 ----
            {
                u64 t0 = fma2(ab0.x, zr1[2*q  ], ab0.y);
                u64 pa = fma2(t0,    zr1[2*q  ], gg.x);
                u64 t1 = fma2(ab1.x, zr1[2*q+1], ab1.y);
                u64 pb = fma2(t1,    zr1[2*q+1], gg.y);
                s21 = add2(s21, pa);
                s21 = add2(s21, pb);
                float a0, a1, b0, b1;
                upk(pa, a0, a1); upk(pb, b0, b1);
                hacc1[2*q  ] = hadd2(hacc1[2*q  ], hex2(cvt_h2(a0, a1)));
                hacc1[2*q+1] = hadd2(hacc1[2*q+1], hex2(cvt_h2(b0, b1)));
            }
        }
        {
            float s0, s1; upk(s20, s0, s1);
            float Sh = s0 + s1;
            float S  = Sh + __shfl_xor_sync(0xffffffffu, Sh, 16);
            float nM = fmaxf(M0, S);
            T0 = T0 * ex2f(M0 - nM) + ex2f(S - nM);
            M0 = nM;
        }
        {
            float s0, s1; upk(s21, s0, s1);
            float Sh = s0 + s1;
            float S  = Sh + __shfl_xor_sync(0xffffffffu, Sh, 16);
            float nM = fmaxf(M1, S);
            T1 = T1 * ex2f(M1 - nM) + ex2f(S - nM);
            M1 = nM;
        }
    }

    // write partials (coalesced per half-warp)
    #pragma unroll
    for (int p = 0; p < 16; p++) {
        d_accP[(ch*NP + half*16 + p)*BATCH + i0] = hacc0[p];
        d_accP[(ch*NP + half*16 + p)*BATCH + i1] = hacc1[p];
    }
    if (half == 0) {
        d_m2P[ch*BATCH + i0] = M0;
        d_t2P[ch*BATCH + i0] = T0;
        d_m2P[ch*BATCH + i1] = M1;
        d_t2P[ch*BATCH + i1] = T1;
    }
}

// ==== kernel 2: stage-1 reduce. grid (32, 32) = 1024 CTAs ==== [R11-exact]
__global__ void __launch_bounds__(256) btc_stage1()
{
    __shared__ float sP[4][64][2];

    const int li = threadIdx.x & 63;
    const int g  = threadIdx.x >> 6;
    const int i  = blockIdx.x * 64 + li;
    const int p  = blockIdx.y;

    float s0 = 0.f, s1 = 0.f;
    #pragma unroll
    for (int c = 0; c < NJ/4; c++) {
        int chn = g*(NJ/4) + c;
        __half2 h = *reinterpret_cast<const __half2*>(&d_accP[(chn*NP + p)*BATCH + i]);
        float2 f = __half22float2(h);
        s0 += f.x; s1 += f.y;
    }
    sP[g][li][0] = s0;
    sP[g][li][1] = s1;
    __syncthreads();

    if (g == 0) {
        float t0 = s0 + sP[1][li][0] + sP[2][li][0] + sP[3][li][0];
        float t1 = s1 + sP[1][li][1] + sP[2][li][1] + sP[3][li][1];
        d_lqp[p*BATCH + i] = lg2f(t0) + lg2f(t1);
    }
}

// ==== kernel 3: finish v2 — grid 64 x 256. CTA = 32 i's x 8 groups ==== [R11-exact]
__global__ void __launch_bounds__(256) btc_finish(const float* __restrict__ zm,
                                                  const float* __restrict__ zl,
                                                  float* __restrict__ out)
{
    __shared__ float s_lqp[8][32];
    __shared__ float s_kl [8][32];
    __shared__ float s_m  [8][32];
    __shared__ float s_t  [8][32];
    __shared__ float sh[256];
    __shared__ unsigned s_done;

    const int li = threadIdx.x & 31;
    const int g  = threadIdx.x >> 5;
    const int i  = blockIdx.x * 32 + li;

    float lqp = 0.f;
    #pragma unroll
    for (int pp = 0; pp < 4; pp++)
        lqp += d_lqp[(g*4 + pp)*BATCH + i];
    s_lqp[g][li] = lqp;

    float M = -1e30f, T = 0.f;
    #pragma unroll
    for (int cc = 0; cc < 8; cc++) {
        const int chn = g*8 + cc;
        float m = d_m2P[chn*BATCH + i];
        float t = d_t2P[chn*BATCH + i];
        float nM = fmaxf(M, m);
        T = T * ex2f(M - nM) + t * ex2f(m - nM);
        M = nM;
    }
    s_m[g][li] = M;
    s_t[g][li] = T;

    {
        float kl = 0.f;
        const float4* m4 = (const float4*)(zm + i*LATENT + g*8);
        const float4* l4 = (const float4*)(zl + i*LATENT + g*8);
        #pragma unroll
        for (int q = 0; q < 2; q++) {
            float4 mm = m4[q], lv = l4[q];
            kl += mm.x*mm.x + ex2f(lv.x*LOG2E_F) - lv.x
                + mm.y*mm.y + ex2f(lv.y*LOG2E_F) - lv.y
                + mm.z*mm.z + ex2f(lv.z*LOG2E_F) - lv.z
                + mm.w*mm.w + ex2f(lv.w*LOG2E_F) - lv.w - 4.f;
        }
        s_kl[g][li] = kl;
    }
    __syncthreads();

    if (g == 0) {
        float lqp_tot = 0.f, kl_tot = 0.f;
        float Mf = -1e30f, Tf = 0.f;
        #pragma unroll
        for (int gg = 0; gg < 8; gg++) {
            lqp_tot += s_lqp[gg][li];
            kl_tot  += s_kl [gg][li];
            float m = s_m[gg][li], t = s_t[gg][li];
            float nM = fmaxf(Mf, m);
            Tf = Tf * ex2f(Mf - nM) + t * ex2f(m - nM);
            Mf = nM;
        }
        float lq2 = Mf + lg2f(Tf);
        d_val[i] = 5.0f * LN2_F * (lq2 - lqp_tot) + 0.5f * kl_tot;
    }
    __syncthreads();

    __threadfence();
    if (threadIdx.x == 0) s_done = atomicAdd(&d_ctr, 1);
    __syncthreads();
    if (s_done == (BATCH/32) - 1) {
        __threadfence();
        float s = 0.f;
        for (int k = threadIdx.x; k < BATCH; k += 256) s += d_val[k];
        sh[threadIdx.x] = s;
        __syncthreads();
        for (int st = 128; st > 0; st >>= 1) {
            if (threadIdx.x < st) sh[threadIdx.x] += sh[threadIdx.x + st];
            __syncthreads();
        }
        if (threadIdx.x == 0) out[0] = sh[0] / (float)BATCH;
    }
}

extern "C" void kernel_launch(void* const* d_in, const int* in_sizes, int n_in,
                              void* d_out, int out_size)
{
    const float* z  = (const float*)d_in[0];
    const float* zm = (const float*)d_in[1];
    const float* zl = (const float*)d_in[2];
    (void)in_sizes; (void)n_in; (void)out_size;

    btc_main<<<dim3(BATCH/IPB, NJ), IB>>>(z, zm, zl);
    btc_stage1<<<dim3(BATCH/64, NP), 256>>>();
    btc_finish<<<BATCH/32, 256>>>(zm, zl, (float*)d_out);
}